// round 5
// baseline (speedup 1.0000x reference)
#include <cuda_runtime.h>
#include <stdint.h>

#define N_NODES 50000
#define N_EDGES 1600000
#define F_IN 128
#define F_H  64
#define F_OUT 32

// ---------------- device scratch (no allocations allowed) ----------------
__device__ int   g_is64;    // edge_index element width (1 = int64)
__device__ int   g_eisel;   // which of (c0, c1) is edge_index (0 or 1)
__device__ int   g_row[N_EDGES];
__device__ int   g_col[N_EDGES];
__device__ int   g_cnt[N_NODES];
__device__ int   g_cur[N_NODES];
__device__ int   g_off[N_NODES + 1];
__device__ float g_dinv[N_NODES];
__device__ int   g_csr_row[N_EDGES];
__device__ float g_csr_nrm[N_EDGES];
__device__ float g_h0[N_NODES * F_H];   // x @ W1
__device__ float g_h [N_NODES * F_H];   // relu(A_hat h0 + b1)
__device__ float g_g [N_NODES * F_H];   // A_hat h

// ---------------- probe: identify edge_index buffer + element width ----------------
// int64 edge values < 50000 => every odd 32-bit word is 0.
// float32 random-normal x => odd words essentially never all zero (1024 samples).
__global__ void k_probe(const int* __restrict__ c0, const int* __restrict__ c1,
                        int tie, int host_eisel) {
    if (blockIdx.x != 0 || threadIdx.x != 0) return;
    if (tie) {
        int any0 = 0;
        for (int i = 1; i < 2048; i += 2) any0 |= c0[i];
        g_eisel = (any0 == 0) ? 0 : 1;
        g_is64 = 1;   // tie only happens when ei is int64 counted as 2x int32 words
    } else {
        g_eisel = host_eisel;
        const int* w = host_eisel ? c1 : c0;
        int any = 0;
        for (int i = 1; i < 2048; i += 2) any |= w[i];
        g_is64 = (any == 0) ? 1 : 0;
    }
}

__global__ void k_decode(const void* __restrict__ c0, const void* __restrict__ c1,
                         int e, int n) {
    int i = blockIdx.x * blockDim.x + threadIdx.x;
    if (i >= e) return;
    const void* p = g_eisel ? c1 : c0;
    int r, c;
    if (g_is64) {
        const long long* q = (const long long*)p;
        r = (int)q[i];
        c = (int)q[e + i];
    } else {
        const int* q = (const int*)p;
        r = q[i];
        c = q[e + i];
    }
    if ((unsigned)r >= (unsigned)n) r = 0;   // defensive: rel_err, not a crash
    if ((unsigned)c >= (unsigned)n) c = 0;
    g_row[i] = r;
    g_col[i] = c;
}

// ---------------- CSR build ----------------
__global__ void k_zero(int n) {
    int i = blockIdx.x * blockDim.x + threadIdx.x;
    if (i < n) { g_cnt[i] = 0; g_cur[i] = 0; }
}

__global__ void k_count(int e) {
    int i = blockIdx.x * blockDim.x + threadIdx.x;
    if (i < e) atomicAdd(&g_cnt[g_col[i]], 1);
}

__global__ void k_dinv(int n) {
    int i = blockIdx.x * blockDim.x + threadIdx.x;
    if (i < n) g_dinv[i] = rsqrtf((float)g_cnt[i] + 1.0f);
}

// single-block exclusive scan over g_cnt -> g_off
__global__ void k_scan(int n) {
    __shared__ int s[1024];
    int t = threadIdx.x;
    int ch = (n + 1023) >> 10;
    int start = t * ch;
    int sum = 0;
    for (int i = 0; i < ch; i++) {
        int idx = start + i;
        if (idx < n) sum += g_cnt[idx];
    }
    s[t] = sum;
    __syncthreads();
    for (int d = 1; d < 1024; d <<= 1) {
        int v = (t >= d) ? s[t - d] : 0;
        __syncthreads();
        s[t] += v;
        __syncthreads();
    }
    int run = (t == 0) ? 0 : s[t - 1];
    for (int i = 0; i < ch; i++) {
        int idx = start + i;
        if (idx < n) { g_off[idx] = run; run += g_cnt[idx]; }
    }
    if (t == 1023) g_off[n] = run;
}

__global__ void k_fill(int e) {
    int i = blockIdx.x * blockDim.x + threadIdx.x;
    if (i < e) {
        int row = g_row[i];
        int col = g_col[i];
        int pos = g_off[col] + atomicAdd(&g_cur[col], 1);
        g_csr_row[pos] = row;
        g_csr_nrm[pos] = g_dinv[row] * g_dinv[col];
    }
}

// ---------------- h0 = x @ W1   (128 -> 64), 4 nodes per block ----------------
__global__ void k_gemm1(const float* __restrict__ c0, const float* __restrict__ c1,
                        const float* __restrict__ W1, int n) {
    __shared__ float Ws[F_IN * F_H];      // 32 KB
    __shared__ float xs[4][F_IN];
    const float* x = g_eisel ? c0 : c1;   // x = the non-edge-index candidate
    int tx = threadIdx.x;                  // 0..63 : out feature
    int ty = threadIdx.y;                  // 0..3  : node in block
    int tid = ty * 64 + tx;
    for (int i = tid; i < F_IN * F_H; i += 256) Ws[i] = W1[i];
    int node = blockIdx.x * 4 + ty;
    for (int i = tx; i < F_IN; i += 64)
        xs[ty][i] = (node < n) ? x[node * F_IN + i] : 0.0f;
    __syncthreads();
    if (node < n) {
        float acc = 0.0f;
#pragma unroll
        for (int k = 0; k < F_IN; k++)
            acc = fmaf(xs[ty][k], Ws[k * F_H + tx], acc);
        g_h0[node * F_H + tx] = acc;
    }
}

// ---------------- warp-per-node gathers (globals referenced IN DEVICE CODE) ----------------
// h = relu(A_hat h0 + b1)
__global__ void k_gather1(const float* __restrict__ bias, int n) {
    int warp = (blockIdx.x * blockDim.x + threadIdx.x) >> 5;
    int lane = threadIdx.x & 31;
    if (warp >= n) return;
    float di = g_dinv[warp];
    float sl = di * di;
    float a0 = g_h0[warp * F_H + lane]      * sl;
    float a1 = g_h0[warp * F_H + 32 + lane] * sl;
    int s = g_off[warp], e = g_off[warp + 1];
    for (int j = s; j < e; j++) {
        int   r = __ldg(&g_csr_row[j]);
        float w = __ldg(&g_csr_nrm[j]);
        a0 = fmaf(g_h0[r * F_H + lane],      w, a0);
        a1 = fmaf(g_h0[r * F_H + 32 + lane], w, a1);
    }
    a0 += bias[lane];
    a1 += bias[32 + lane];
    g_h[warp * F_H + lane]      = fmaxf(a0, 0.0f);
    g_h[warp * F_H + 32 + lane] = fmaxf(a1, 0.0f);
}

// g = A_hat h
__global__ void k_gather2(int n) {
    int warp = (blockIdx.x * blockDim.x + threadIdx.x) >> 5;
    int lane = threadIdx.x & 31;
    if (warp >= n) return;
    float di = g_dinv[warp];
    float sl = di * di;
    float a0 = g_h[warp * F_H + lane]      * sl;
    float a1 = g_h[warp * F_H + 32 + lane] * sl;
    int s = g_off[warp], e = g_off[warp + 1];
    for (int j = s; j < e; j++) {
        int   r = __ldg(&g_csr_row[j]);
        float w = __ldg(&g_csr_nrm[j]);
        a0 = fmaf(g_h[r * F_H + lane],      w, a0);
        a1 = fmaf(g_h[r * F_H + 32 + lane], w, a1);
    }
    g_g[warp * F_H + lane]      = a0;
    g_g[warp * F_H + 32 + lane] = a1;
}

// ---------------- output heads ----------------
__global__ void k_out(const float* __restrict__ Wmu, const float* __restrict__ bmu,
                      const float* __restrict__ Wls, const float* __restrict__ bls,
                      float* __restrict__ out, int n) {
    __shared__ float Wm[F_H * F_OUT];
    __shared__ float Wl[F_H * F_OUT];
    __shared__ float gs[8][F_H];
    int tx = threadIdx.x;                 // 0..31 : out feature
    int ty = threadIdx.y;                 // 0..7  : node in block
    int tid = ty * 32 + tx;
    for (int i = tid; i < F_H * F_OUT; i += 256) { Wm[i] = Wmu[i]; Wl[i] = Wls[i]; }
    int node = blockIdx.x * 8 + ty;
    for (int i = tx; i < F_H; i += 32)
        gs[ty][i] = (node < n) ? g_g[node * F_H + i] : 0.0f;
    __syncthreads();
    if (node < n) {
        float am = 0.0f, al = 0.0f;
#pragma unroll
        for (int k = 0; k < F_H; k++) {
            float v = gs[ty][k];
            am = fmaf(v, Wm[k * F_OUT + tx], am);
            al = fmaf(v, Wl[k * F_OUT + tx], al);
        }
        out[node * F_OUT + tx]             = am + bmu[tx];
        out[n * F_OUT + node * F_OUT + tx] = al + bls[tx];
    }
}

// ---------------- launch ----------------
extern "C" void kernel_launch(void* const* d_in, const int* in_sizes, int n_in,
                              void* d_out, int out_size) {
    // n from the output buffer itself: [mu | logstd], each n*32 floats
    int n = out_size / (2 * F_OUT);

    // Two largest inputs: x (n*128) and edge_index (2E elems; possibly 4E int32 words)
    long long best1 = -1, best2 = -1; int i1 = -1, i2 = -1;
    for (int i = 0; i < n_in; i++) {
        long long s = in_sizes[i];
        if (s > best1) { best2 = best1; i2 = i1; best1 = s; i1 = i; }
        else if (s > best2) { best2 = s; i2 = i; }
    }
    int tie = (best1 == best2);

    int idx_W1 = -1, idx_b1 = -1;
    int idx_W_a = -1, idx_W_b = -1, idx_b_a = -1, idx_b_b = -1;
    for (int i = 0; i < n_in; i++) {
        if (i == i1 || i == i2) continue;
        int s = in_sizes[i];
        if (s == F_IN * F_H) idx_W1 = i;
        else if (s == F_H) idx_b1 = i;
        else if (s == F_H * F_OUT) { if (idx_W_a < 0) idx_W_a = i; else idx_W_b = i; }
        else if (s == F_OUT) { if (idx_b_a < 0) idx_b_a = i; else idx_b_b = i; }
    }
    // Large tensors at the front => insertion order (mu before ls);
    // at the back => alphabetical (W_ls before W_mu).
    int min_big = (i1 < i2) ? i1 : i2;
    int mu_first = (min_big == 0) ? 1 : 0;
    int idx_Wmu = mu_first ? idx_W_a : idx_W_b;
    int idx_Wls = mu_first ? idx_W_b : idx_W_a;
    int idx_bmu = mu_first ? idx_b_a : idx_b_b;
    int idx_bls = mu_first ? idx_b_b : idx_b_a;

    int ca = (i1 < i2) ? i1 : i2;
    int cb = (i1 < i2) ? i2 : i1;
    const float* c0 = (const float*)d_in[ca];
    const float* c1 = (const float*)d_in[cb];

    int e, host_eisel = 0;
    if (tie) {
        e = in_sizes[ca] / 4;              // int64 counted as int32 words: 4E
    } else {
        int idx_x  = (in_sizes[ca] > in_sizes[cb]) ? ca : cb;
        int idx_ei = (idx_x == ca) ? cb : ca;
        e = in_sizes[idx_ei] / 2;          // 2E elements (int32 or int64)
        host_eisel = (idx_ei == cb) ? 1 : 0;
        if (n <= 0) n = in_sizes[idx_x] / F_IN;
    }
    if (n <= 0 && tie) n = in_sizes[ca] / F_IN;
    if (n > N_NODES) n = N_NODES;
    if (e > N_EDGES) e = N_EDGES;

    const float* W1  = (const float*)d_in[idx_W1];
    const float* b1  = (const float*)d_in[idx_b1];
    const float* Wmu = (const float*)d_in[idx_Wmu];
    const float* bmu = (const float*)d_in[idx_bmu];
    const float* Wls = (const float*)d_in[idx_Wls];
    const float* bls = (const float*)d_in[idx_bls];
    float* out = (float*)d_out;

    k_probe <<<1, 32>>>((const int*)c0, (const int*)c1, tie, host_eisel);
    k_decode<<<(e + 255) / 256, 256>>>((const void*)c0, (const void*)c1, e, n);

    k_zero <<<(n + 255) / 256, 256>>>(n);
    k_count<<<(e + 255) / 256, 256>>>(e);
    k_dinv <<<(n + 255) / 256, 256>>>(n);
    k_scan <<<1, 1024>>>(n);
    k_fill <<<(e + 255) / 256, 256>>>(e);

    k_gemm1<<<(n + 3) / 4, dim3(64, 4)>>>(c0, c1, W1, n);

    int blocks = (n + 7) / 8;   // 8 warps (256 threads) per block
    k_gather1<<<blocks, 256>>>(b1, n);
    k_gather2<<<blocks, 256>>>(n);

    k_out<<<(n + 7) / 8, dim3(32, 8)>>>(Wmu, bmu, Wls, bls, out, n);
}